// round 7
// baseline (speedup 1.0000x reference)
#include <cuda_runtime.h>
#include <cstdint>

#define Hh 576
#define Ww 640
#define HW (Hh*Ww)
#define BIGF 1e10f
#define EPSF 1e-5f

#define GRID 740            // 148 SMs x 5 blocks/SM guaranteed co-resident
#define BT   256
#define NTHR (GRID*BT)

// ---- scratch (__device__ globals; zero-initialized at module load) ----
// Depth keys: key = ~bits(z); z>0 => key>0x80000000; key==0 means empty.
// min(z) = decode(max key). Final phase resets keys to 0 => replay invariant.
__device__ unsigned int g_depth_key[HW];
__device__ float        g_patchmin[HW];
__device__ float4       g_acc4[HW];
__device__ unsigned int g_bar_arrive;   // self-resetting
__device__ unsigned int g_bar_gen;      // monotone generation counter

__device__ __forceinline__ void red_add_v4(float4* p, float a, float b, float c, float d) {
    asm volatile("red.global.add.v4.f32 [%0], {%1,%2,%3,%4};"
                 :: "l"(__cvta_generic_to_global(p)),
                    "f"(a), "f"(b), "f"(c), "f"(d) : "memory");
}
__device__ __forceinline__ void red_add_f32(float* p, float v) {
    asm volatile("red.global.add.f32 [%0], %1;"
                 :: "l"(__cvta_generic_to_global(p)), "f"(v) : "memory");
}

// sense-reversing grid barrier (all GRID blocks are co-resident by construction)
__device__ __forceinline__ void grid_barrier() {
    __syncthreads();
    if (threadIdx.x == 0) {
        __threadfence();
        unsigned gen = *(volatile unsigned*)&g_bar_gen;
        if (atomicAdd(&g_bar_arrive, 1u) == GRID - 1) {
            g_bar_arrive = 0;
            __threadfence();
            *(volatile unsigned*)&g_bar_gen = gen + 1;
        } else {
            while (*(volatile unsigned*)&g_bar_gen == gen) __nanosleep(64);
        }
        __threadfence();
    }
    __syncthreads();
}

#define TW 32
#define TH 8
#define SW (TW + 4)
#define SH (TH + 4)
#define NTILES ((Ww/TW)*(Hh/TH))   // 1440
#define NPB (HW/BT)                // 1440 pixel-blocks for final

__global__ void __launch_bounds__(BT, 5) k_render(
        const float* __restrict__ pts,
        const float* __restrict__ color,
        const float* __restrict__ imw,
        const int*   __restrict__ mask,
        const float* __restrict__ thresh,
        float* __restrict__ out_depth,
        float* __restrict__ out_color,
        float* __restrict__ out_imw,
        float* __restrict__ out_weight,
        float* __restrict__ out_vis,
        int n) {
    __shared__ union {
        unsigned int tile[SH * SW];   // patchmin
        float sc[BT * 3];             // final color staging
    } sm;

    const int tid  = threadIdx.x;
    const int gtid = blockIdx.x * BT + tid;

    // ================= phase 1: z-buffer scatter-min =================
    for (int i = gtid; i < n; i += NTHR) {
        float x = __ldg(&pts[3*i]), y = __ldg(&pts[3*i+1]), z = __ldg(&pts[3*i+2]);
        int px = __float2int_rd(x), py = __float2int_rd(y);
        bool valid = (px >= 0) & (px < Ww) & (py >= 0) & (py < Hh) & (mask[i] > 0);
        if (valid)
            atomicMax(&g_depth_key[py * Ww + px], ~__float_as_uint(z));
    }
    grid_barrier();

    // ====== phase 2: 5x5 patch-min + depth output + acc zeroing ======
    for (int t = blockIdx.x; t < NTILES; t += GRID) {
        int bx = t % (Ww / TW);
        int by = t / (Ww / TW);
        int x0 = bx * TW, y0 = by * TH;

        #pragma unroll
        for (int k = tid; k < SH * SW; k += BT) {
            int ly = k / SW, lx = k % SW;
            int gy = y0 + ly - 2, gx = x0 + lx - 2;
            unsigned v = 0u;
            if (gy >= 0 && gy < Hh && gx >= 0 && gx < Ww)
                v = __ldcg(&g_depth_key[gy * Ww + gx]);
            sm.tile[k] = v;
        }
        __syncthreads();

        int tx = tid % TW, ty = tid / TW;
        unsigned m = 0u;
        #pragma unroll
        for (int dy = 0; dy < 5; ++dy)
            #pragma unroll
            for (int dx = 0; dx < 5; ++dx)
                m = max(m, sm.tile[(ty + dy) * SW + (tx + dx)]);
        int gi = (y0 + ty) * Ww + (x0 + tx);
        g_patchmin[gi] = (m == 0u) ? BIGF : __uint_as_float(~m);
        unsigned ck = sm.tile[(ty + 2) * SW + (tx + 2)];
        out_depth[gi] = ck ? __uint_as_float(~ck) : 0.f;
        g_acc4[gi] = make_float4(0.f, 0.f, 0.f, 0.f);
        out_weight[gi] = 0.f;
        __syncthreads();   // protect tile before next iteration
    }
    grid_barrier();

    // ============== phase 3: visibility + 7x7 warp splat ==============
    {
        int lane = tid & 31;
        int u1 = lane + 32;
        int ox0 = lane % 7 - 3, oy0 = lane / 7 - 3;
        int ox1 = u1 % 7 - 3,   oy1 = u1 / 7 - 3;
        float cxo0 = (float)ox0 + 0.5f, cyo0 = (float)oy0 + 0.5f;
        float cxo1 = (float)ox1 + 0.5f, cyo1 = (float)oy1 + 0.5f;
        int ioff0 = oy0 * Ww + ox0;
        int ioff1 = oy1 * Ww + ox1;
        bool has1 = (u1 < 49);
        float th = __ldg(thresh);

        for (int i0 = gtid; i0 - lane < n; i0 += NTHR) {
            int i = i0;
            int warp_base = i - lane;
            bool vis = false;
            if (i < n) {
                float x = pts[3*i], y = pts[3*i+1], z = pts[3*i+2];
                int px = __float2int_rd(x), py = __float2int_rd(y);
                bool valid = (px >= 0) & (px < Ww) & (py >= 0) & (py < Hh) & (mask[i] > 0);
                int ccx = min(max(px, 0), Ww - 1);
                int ccy = min(max(py, 0), Hh - 1);
                float pm = __ldcg(&g_patchmin[ccy * Ww + ccx]);
                vis = valid && (z <= pm + th);
                out_vis[i] = vis ? 1.0f : 0.0f;
            }
            unsigned vm = __ballot_sync(0xffffffffu, vis);
            while (vm) {
                int src = __ffs(vm) - 1;
                vm &= vm - 1;
                int j = warp_base + src;     // warp-uniform broadcast loads
                float xx = __ldg(&pts[3*j]);
                float yy = __ldg(&pts[3*j+1]);
                float s0 = __ldg(&color[3*j]);
                float s1 = __ldg(&color[3*j+1]);
                float s2 = __ldg(&color[3*j+2]);
                float swv = __ldg(&imw[j]);
                int pxb = __float2int_rd(xx);
                int pyb = __float2int_rd(yy);
                float fx = (float)pxb - xx;
                float fy = (float)pyb - yy;
                int base = pyb * Ww + pxb;
                {
                    int sx = pxb + ox0, sy = pyb + oy0;
                    if (((unsigned)sx < Ww) & ((unsigned)sy < Hh)) {
                        float dx = fx + cxo0, dy = fy + cyo0;
                        float w = __fdividef(1.0f, fmaf(dx, dx, fmaf(dy, dy, EPSF)));
                        int idx = base + ioff0;
                        red_add_v4(&g_acc4[idx], w * s0, w * s1, w * s2, w * swv);
                        red_add_f32(&out_weight[idx], w);
                    }
                }
                if (has1) {
                    int sx = pxb + ox1, sy = pyb + oy1;
                    if (((unsigned)sx < Ww) & ((unsigned)sy < Hh)) {
                        float dx = fx + cxo1, dy = fy + cyo1;
                        float w = __fdividef(1.0f, fmaf(dx, dx, fmaf(dy, dy, EPSF)));
                        int idx = base + ioff1;
                        red_add_v4(&g_acc4[idx], w * s0, w * s1, w * s2, w * swv);
                        red_add_f32(&out_weight[idx], w);
                    }
                }
            }
        }
    }
    grid_barrier();

    // === phase 4: acc4 -> color/imw (smem-staged coalesced) + key reset ===
    for (int pb = blockIdx.x; pb < NPB; pb += GRID) {
        int i = pb * BT + tid;
        float4 a = __ldcg(&g_acc4[i]);
        sm.sc[tid * 3 + 0] = a.x;        // stride-3 smem: conflict-free
        sm.sc[tid * 3 + 1] = a.y;
        sm.sc[tid * 3 + 2] = a.z;
        out_imw[i] = a.w;
        g_depth_key[i] = 0u;             // reset for next replay
        __syncthreads();
        if (tid < 192)
            reinterpret_cast<float4*>(out_color)[pb * 192 + tid] =
                reinterpret_cast<const float4*>(sm.sc)[tid];
        __syncthreads();
    }
}

extern "C" void kernel_launch(void* const* d_in, const int* in_sizes, int n_in,
                              void* d_out, int out_size) {
    const float* pts    = (const float*)d_in[0];
    const float* color  = (const float*)d_in[1];
    const float* imw    = (const float*)d_in[2];
    const int*   mask   = (const int*)  d_in[3];
    const float* thresh = (const float*)d_in[4];
    int n = in_sizes[3];

    float* out = (float*)d_out;
    float* out_depth  = out;
    float* out_color  = out + HW;
    float* out_imw    = out + HW * 4;
    float* out_weight = out + HW * 5;
    float* out_vis    = out + HW * 6;

    k_render<<<GRID, BT>>>(pts, color, imw, mask, thresh,
                           out_depth, out_color, out_imw, out_weight, out_vis, n);
}